// round 17
// baseline (speedup 1.0000x reference)
#include <cuda_runtime.h>
#include <cuda_bf16.h>

// ChamferLoss R16 = R14 (37.6us best) with q held in REGISTERS.
// R14 reloaded the same 256 columns (8x LDS.128) every rg iteration; q is
// loop-invariant per warp and fits in 16 ull regs (x,y,z,halfnorm packed
// pairs for 8 columns/lane) - the same space the transient loads used.
// Each lane loads its columns straight from global (coalesced float4) and
// packs once; q SMEM arrays removed. Everything else is R14: 512 thr,
// 16 warps = 4 row-blocks x 4 col-quarters, RG=8, colmin[8] regs,
// u = 0.5*d^2 via packed f32x2 FMA (norms folded into accumulator init),
// sqrt hoisted outside mins, REDUX.MIN row mins + SMEM atomicMin merges,
// fused deterministic final reduction via done-ticket. One CTA per pair.

#define NPTS    1024
#define THREADS 512
#define NWARPS  16
#define RG      8
#define CB_MAX  128

typedef unsigned long long ull;

#define PACK2(d, lo, hi) \
    asm("mov.b64 %0, {%1,%2};" : "=l"(d) : "f"(lo), "f"(hi))
#define UNPACK2(lo, hi, s) \
    asm("mov.b64 {%0,%1}, %2;" : "=f"(lo), "=f"(hi) : "l"(s))
#define FMA2(d, a, b, c) \
    asm("fma.rn.f32x2 %0, %1, %2, %3;" : "=l"(d) : "l"(a), "l"(b), "l"(c))
#define ADD2(d, a, b) \
    asm("add.rn.f32x2 %0, %1, %2;" : "=l"(d) : "l"(a), "l"(b))

__device__ float g_partials[CB_MAX];
__device__ int   g_done;   // zero-init; reset by last CTA each run

__global__ __launch_bounds__(THREADS, 1)
void chamfer_pair_kernel(const float* __restrict__ p, const float* __restrict__ q,
                         float* __restrict__ out, int cb_count) {
    __shared__ __align__(16) float px_s[NPTS], py_s[NPTS], pz_s[NPTS], ps_s[NPTS];
    __shared__ unsigned rowmin_sh[NPTS];
    __shared__ unsigned colmin_sh[NPTS];
    __shared__ float sred[NWARPS];
    __shared__ int sh_last;

    const int cb   = blockIdx.x;
    const int tid  = threadIdx.x;
    const int warp = tid >> 5;
    const int lane = tid & 31;
    const int rb = warp >> 2;          // row block 0..3   (256 rows)
    const int cq = warp & 3;           // column quarter 0..3 (256 cols)
    const float INF = __int_as_float(0x7f800000);

    const float4* __restrict__ qp = reinterpret_cast<const float4*>(q) + (size_t)cb * NPTS;
    const float4* __restrict__ pp = reinterpret_cast<const float4*>(p) + (size_t)cb * NPTS;

    // Stage p (SoA, negated, half-norms); init min buffers.
    for (int i = tid; i < NPTS; i += THREADS) {
        float4 u = pp[i];
        px_s[i] = -u.y; py_s[i] = -u.z; pz_s[i] = -u.w;
        ps_s[i] = 0.5f * (u.y * u.y + u.z * u.z + u.w * u.w);
        rowmin_sh[i] = 0x7f800000u;
        colmin_sh[i] = 0x7f800000u;
    }

    // Load this lane's 8 q columns from GLOBAL (coalesced float4) and pack:
    // cols = cq*256 + j4*128 + lane*4 + {0..3}, j4 = 0..1.
    const int colbase0 = (cq << 8) + (lane << 2);
    ulonglong2 qxx[2], qyy[2], qzz[2], qss[2];
    #pragma unroll
    for (int j4 = 0; j4 < 2; ++j4) {
        const int c0 = colbase0 + (j4 << 7);
        float4 v0 = qp[c0 + 0];
        float4 v1 = qp[c0 + 1];
        float4 v2 = qp[c0 + 2];
        float4 v3 = qp[c0 + 3];
        PACK2(qxx[j4].x, v0.y, v1.y);  PACK2(qxx[j4].y, v2.y, v3.y);
        PACK2(qyy[j4].x, v0.z, v1.z);  PACK2(qyy[j4].y, v2.z, v3.z);
        PACK2(qzz[j4].x, v0.w, v1.w);  PACK2(qzz[j4].y, v2.w, v3.w);
        float s0 = 0.5f * (v0.y * v0.y + v0.z * v0.z + v0.w * v0.w);
        float s1 = 0.5f * (v1.y * v1.y + v1.z * v1.z + v1.w * v1.w);
        float s2 = 0.5f * (v2.y * v2.y + v2.z * v2.z + v2.w * v2.w);
        float s3 = 0.5f * (v3.y * v3.y + v3.z * v3.z + v3.w * v3.w);
        PACK2(qss[j4].x, s0, s1);      PACK2(qss[j4].y, s2, s3);
    }
    __syncthreads();

    float colmin[8];
    #pragma unroll
    for (int j = 0; j < 8; ++j) colmin[j] = INF;

    #pragma unroll 1
    for (int rg = 0; rg < 32; ++rg) {              // 32 groups of 8 rows
        const int row0 = rb * 256 + rg * RG;
        ull pnx2[RG], pny2[RG], pnz2[RG], psq2[RG];
        float rmin[RG];
        #pragma unroll
        for (int r = 0; r < RG; ++r) {
            int row = row0 + r;
            float a = px_s[row], b = py_s[row];    // broadcast LDS
            float c = pz_s[row], s = ps_s[row];
            PACK2(pnx2[r], a, a);
            PACK2(pny2[r], b, b);
            PACK2(pnz2[r], c, c);
            PACK2(psq2[r], s, s);
            rmin[r] = INF;
        }
        #pragma unroll
        for (int j4 = 0; j4 < 2; ++j4) {           // q already in registers
            #pragma unroll
            for (int r = 0; r < RG; ++r) {
                ull a01, a23;
                ADD2(a01, qss[j4].x, psq2[r]);     // 0.5|q|^2 + 0.5|p|^2
                ADD2(a23, qss[j4].y, psq2[r]);
                FMA2(a01, pnx2[r], qxx[j4].x, a01);   // - px*qx
                FMA2(a23, pnx2[r], qxx[j4].y, a23);
                FMA2(a01, pny2[r], qyy[j4].x, a01);
                FMA2(a23, pny2[r], qyy[j4].y, a23);
                FMA2(a01, pnz2[r], qzz[j4].x, a01);   // = 0.5*d2, 4 columns
                FMA2(a23, pnz2[r], qzz[j4].y, a23);
                float u0, u1, u2, u3;
                UNPACK2(u0, u1, a01);
                UNPACK2(u2, u3, a23);
                colmin[4 * j4 + 0] = fminf(colmin[4 * j4 + 0], u0);
                colmin[4 * j4 + 1] = fminf(colmin[4 * j4 + 1], u1);
                colmin[4 * j4 + 2] = fminf(colmin[4 * j4 + 2], u2);
                colmin[4 * j4 + 3] = fminf(colmin[4 * j4 + 3], u3);
                rmin[r] = fminf(rmin[r], fminf(fminf(u0, u1), fminf(u2, u3)));
            }
        }
        // Row mins over this warp's 256 cols: REDUX.MIN on clamped bits.
        #pragma unroll
        for (int r = 0; r < RG; ++r) {
            unsigned mb = __float_as_uint(fmaxf(rmin[r], 0.0f));
            mb = __reduce_min_sync(0xffffffffu, mb);
            if (lane == 0)
                atomicMin(&rowmin_sh[row0 + r], mb);  // merge 4 col-quarter warps
        }
    }

    // Column-min merge (4 row-block warps share each column quarter).
    #pragma unroll
    for (int j4 = 0; j4 < 2; ++j4) {
        #pragma unroll
        for (int k = 0; k < 4; ++k) {
            int c = colbase0 + (j4 << 7) + k;
            float v = fmaxf(colmin[4 * j4 + k], 0.0f);
            atomicMin(&colmin_sh[c], __float_as_uint(v));
        }
    }
    __syncthreads();

    // Per-thread partial: 2 rows + 2 cols each, fixed order (u = 0.5*d2).
    float acc = 0.0f;
    for (int i = tid; i < NPTS; i += THREADS) {
        acc += sqrtf(2.0f * __uint_as_float(rowmin_sh[i]) + 1e-12f);
        acc += sqrtf(2.0f * __uint_as_float(colmin_sh[i]) + 1e-12f);
    }
    #pragma unroll
    for (int off = 16; off > 0; off >>= 1)
        acc += __shfl_xor_sync(0xffffffffu, acc, off);
    if (lane == 0) sred[warp] = acc;
    __syncthreads();

    // Per-CTA total + done-ticket.
    if (tid == 0) {
        float total = 0.0f;
        #pragma unroll
        for (int w = 0; w < NWARPS; ++w) total += sred[w];
        g_partials[cb] = total;
        __threadfence();                       // partial visible before ticket
        int prev = atomicAdd(&g_done, 1);
        sh_last = (prev == cb_count - 1) ? 1 : 0;
    }
    __syncthreads();

    // Last CTA: deterministic fixed-order final reduction over all pairs.
    if (sh_last) {
        __threadfence();                       // observe all partials (L2)
        float v = (tid < cb_count) ? __ldcg(&g_partials[tid]) : 0.0f;
        #pragma unroll
        for (int off = 16; off > 0; off >>= 1)
            v += __shfl_xor_sync(0xffffffffu, v, off);
        if (lane == 0) sred[warp] = v;
        __syncthreads();
        if (tid == 0) {
            float tot = 0.0f;
            #pragma unroll
            for (int w = 0; w < NWARPS; ++w) tot += sred[w];
            out[0] = tot;
            g_done = 0;                        // reset for next graph replay
        }
    }
}

extern "C" void kernel_launch(void* const* d_in, const int* in_sizes, int n_in,
                              void* d_out, int out_size) {
    const float* p = (const float*)d_in[0];
    const float* q = (const float*)d_in[1];
    float* out = (float*)d_out;

    int cb = in_sizes[0] / (NPTS * 4);   // = 128 for (2,64,1024,4)
    if (cb > CB_MAX) cb = CB_MAX;

    chamfer_pair_kernel<<<cb, THREADS>>>(p, q, out, cb);
}